// round 15
// baseline (speedup 1.0000x reference)
#include <cuda_runtime.h>
#include <cuda_fp16.h>
#include <mma.h>
#include <math.h>
#include <stdint.h>

using namespace nvcuda;

// Problem constants
#define Bq   64
#define Tt   256
#define Ss   512
#define Hh   1024
#define G4H  4096
#define HD   512
#define Aa   64
#define NOUT 64
#define MROWS (Bq * Tt)   // 16384
#define NBLK 128

// ---------------- scratch (device globals; no runtime allocation) ----------
// g_xp layout: [t][b][4H]  (step-major => per-step reads are one 1MB slab)
__device__ float  g_xp[(size_t)MROWS * G4H];
__device__ __half g_xh[(size_t)MROWS * Ss];    // x in fp16 [16384, 512]
__device__ __half g_wxT[(size_t)G4H * Ss];     // W_x^T in fp16 [4096, 512]
__device__ __half g_h16[2][Bq * Hh];           // ping-pong hidden state fp16, [m][k]
__device__ float  g_hid[Bq * HD];              // relu dense head
__device__ unsigned g_bar;                     // grid barrier counter

// ======================= helpers ========================
__device__ __forceinline__ uint32_t smem_u32(const void* p) {
    uint32_t a;
    asm("{ .reg .u64 t; cvta.to.shared.u64 t, %1; cvt.u32.u64 %0, t; }"
        : "=r"(a) : "l"(p));
    return a;
}
#define CP_ASYNC16(dst, src) \
    asm volatile("cp.async.cg.shared.global [%0], [%1], 16;" :: "r"(dst), "l"(src))
#define CP_COMMIT() asm volatile("cp.async.commit_group;" ::: "memory")
#define CP_WAIT(n)  asm volatile("cp.async.wait_group %0;" :: "n"(n) : "memory")

// =====================================================================
// Conversion: x (fp32) -> g_xh (fp16)
// =====================================================================
__global__ __launch_bounds__(256) void k_cvt_x(const float* __restrict__ X)
{
    size_t i = ((size_t)blockIdx.x * 256 + threadIdx.x) * 4;
    float4 v = *(const float4*)(X + i);
    *(__half2*)(g_xh + i)     = __floats2half2_rn(v.x, v.y);
    *(__half2*)(g_xh + i + 2) = __floats2half2_rn(v.z, v.w);
}

// =====================================================================
// Conversion: W_x [512, 4096] fp32 -> g_wxT [4096, 512] fp16 (transpose)
// =====================================================================
__global__ __launch_bounds__(256) void k_cvt_wT(const float* __restrict__ Wx)
{
    __shared__ float t[32][33];
    const int nb = blockIdx.x * 32;
    const int kb = blockIdx.y * 32;
    const int tx = threadIdx.x & 31;
    const int ty = threadIdx.x >> 5;
#pragma unroll
    for (int r = ty; r < 32; r += 8)
        t[r][tx] = Wx[(size_t)(kb + r) * G4H + nb + tx];
    __syncthreads();
#pragma unroll
    for (int r = ty; r < 32; r += 8)
        g_wxT[(size_t)(nb + r) * Ss + kb + tx] = __float2half_rn(t[tx][r]);
}

// =====================================================================
// Kernel 1: x_proj = x @ W_x via wmma (HMMA fp16, fp32 accumulate).
// Block tile 128x128, BK=32, 8 warps (2m x 4n), warp tile 64x32.
// Output written in [t][b][4H] layout: row r=(b*256+t) -> slab t, row b.
// 16-row tiles never cross a batch boundary (256 % 16 == 0), so
// consecutive tile rows advance t by 1 => ldm = 64*4096.
// =====================================================================
#define BM 128
#define BN 128
#define BK 32
#define LDSB (BK + 8)   // 40 halfs = 80 bytes

__global__ __launch_bounds__(256) void k_xproj_mma()
{
    __shared__ __half sA[BM][LDSB];
    __shared__ __half sB[BN][LDSB];

    const int tid = threadIdx.x;
    const int wid = tid >> 5;
    const int wm  = wid & 1;
    const int wn  = wid >> 1;
    const int bm  = blockIdx.y * BM;
    const int bn  = blockIdx.x * BN;

    wmma::fragment<wmma::accumulator, 16, 16, 16, float> acc[4][2];
#pragma unroll
    for (int i = 0; i < 4; i++)
#pragma unroll
        for (int j = 0; j < 2; j++)
            wmma::fill_fragment(acc[i][j], 0.0f);

    const int sr = tid >> 1;
    const int sc = (tid & 1) * 16;

    for (int k0 = 0; k0 < Ss; k0 += BK) {
        __syncthreads();
        {
            const uint4* sa = (const uint4*)(g_xh  + (size_t)(bm + sr) * Ss + k0 + sc);
            *(uint4*)&sA[sr][sc]     = sa[0];
            *(uint4*)&sA[sr][sc + 8] = sa[1];
            const uint4* sb = (const uint4*)(g_wxT + (size_t)(bn + sr) * Ss + k0 + sc);
            *(uint4*)&sB[sr][sc]     = sb[0];
            *(uint4*)&sB[sr][sc + 8] = sb[1];
        }
        __syncthreads();

#pragma unroll
        for (int kk = 0; kk < BK; kk += 16) {
            wmma::fragment<wmma::matrix_a, 16, 16, 16, __half, wmma::row_major> af[4];
            wmma::fragment<wmma::matrix_b, 16, 16, 16, __half, wmma::col_major> bf[2];
#pragma unroll
            for (int i = 0; i < 4; i++)
                wmma::load_matrix_sync(af[i], &sA[wm * 64 + i * 16][kk], LDSB);
#pragma unroll
            for (int j = 0; j < 2; j++)
                wmma::load_matrix_sync(bf[j], &sB[wn * 32 + j * 16][kk], LDSB);
#pragma unroll
            for (int i = 0; i < 4; i++)
#pragma unroll
                for (int j = 0; j < 2; j++)
                    wmma::mma_sync(acc[i][j], af[i], bf[j], acc[i][j]);
        }
    }

#pragma unroll
    for (int i = 0; i < 4; i++) {
        const int r0 = bm + wm * 64 + i * 16;
        const int t0 = r0 & 255;
        const int b0 = r0 >> 8;
#pragma unroll
        for (int j = 0; j < 2; j++)
            wmma::store_matrix_sync(
                g_xp + ((size_t)t0 * Bq + b0) * G4H + bn + wn * 32 + j * 16,
                acc[i][j], (unsigned)(Bq * G4H), wmma::mem_row_major);
    }
}

// =====================================================================
// Kernel 2: persistent LSTM recurrence on tensor cores.
// 128 blocks x 256 threads. Block b owns 8 hidden units (32 z-columns).
// W_h cols in smem fp16 col-major (once). Per step: cp.async the FULL
// 64x1024 fp16 h tile in 2 commit groups (pipelined against the MMA of
// group 0), 8 warps each compute one 16x16 tile of the 64x32 z-tile,
// gates read the step-t slab of g_xp ([t][b][4H]), grid barrier.
// =====================================================================
#define WS_LD 1032
#define SH_LD 1032
#define ZS_LD 40
#define P_WS_OFF 0
#define P_SH_OFF 66048                      // 32*1032*2
#define P_ZS_OFF (66048 + 132096)           // + 64*1032*2
#define P_SMEM   (P_ZS_OFF + 10240)         // + 64*40*4  = 208384 B

__global__ __launch_bounds__(256, 1) void k_persist(const float* __restrict__ Wh,
                                                    const float* __restrict__ bias)
{
    extern __shared__ char psm[];
    __half* wsB = (__half*)(psm + P_WS_OFF);   // [32][1032] col-major W_h fp16
    __half* shh = (__half*)(psm + P_SH_OFF);   // [64][1032] full h tile fp16
    float*  zsf = (float*)(psm + P_ZS_OFF);    // [64][40]   z tile fp32

    const int tid = threadIdx.x;
    const int j0  = blockIdx.x * 8;

    // ---- stage this block's 32 W_h columns as fp16 (once) ----
    for (int idx = tid; idx < 32768; idx += 256) {
        int c = idx & 31, k = idx >> 5;
        wsB[c * WS_LD + k] =
            __float2half_rn(Wh[(size_t)k * G4H + (c >> 3) * Hh + j0 + (c & 7)]);
    }

    // ---- warp tile mapping (8 warps -> 4 row tiles x 2 col tiles) ----
    const int w  = tid >> 5;
    const int rt = w & 3;          // rows rt*16..+15
    const int ct = w >> 2;         // cols ct*16..+15

    // ---- cp.async staging: per group 4096 16B-units, 16 per thread ----
    const uint32_t shh_u = smem_u32(psm) + P_SH_OFF;

    // ---- gate mapping ----
    const int gjj = tid & 7;
    const int gm0 = tid >> 3;      // 0..31
    const int gm1 = gm0 + 32;
    float bb[4];
#pragma unroll
    for (int g = 0; g < 4; g++) bb[g] = bias[g * Hh + j0 + gjj];

    float cc0 = 0.f, cc1 = 0.f;
    __syncthreads();

    for (int t = 0; t < Tt; t++) {
        const __half* __restrict__ hin  = g_h16[t & 1];
        __half* __restrict__       hout = g_h16[(t + 1) & 1];

        // prefetch xp for the gate phase (step-t slab, contiguous in memory)
        float xg0[4], xg1[4];
#pragma unroll
        for (int g = 0; g < 4; g++) {
            const size_t cb = (size_t)g * Hh + j0 + gjj;
            xg0[g] = g_xp[((size_t)t * Bq + gm0) * G4H + cb];
            xg1[g] = g_xp[((size_t)t * Bq + gm1) * G4H + cb];
        }

        // stage h: two commit groups of 512 cols each
#pragma unroll
        for (int grp = 0; grp < 2; grp++) {
#pragma unroll
            for (int i = 0; i < 16; i++) {
                int u   = i * 256 + tid;
                int row = u >> 6;
                int cu  = u & 63;
                uint32_t dst = shh_u + (uint32_t)(row * SH_LD + grp * 512 + cu * 8) * 2u;
                const __half* src = hin + (size_t)row * Hh + grp * 512 + cu * 8;
                CP_ASYNC16(dst, src);
            }
            CP_COMMIT();
        }

        wmma::fragment<wmma::accumulator, 16, 16, 16, float> acc;
        wmma::fill_fragment(acc, 0.0f);

        CP_WAIT(1);
        __syncthreads();
#pragma unroll
        for (int kk = 0; kk < 32; kk++) {
            wmma::fragment<wmma::matrix_a, 16, 16, 16, __half, wmma::row_major> af;
            wmma::fragment<wmma::matrix_b, 16, 16, 16, __half, wmma::col_major> bf;
            wmma::load_matrix_sync(af, shh + rt * 16 * SH_LD + kk * 16, SH_LD);
            wmma::load_matrix_sync(bf, wsB + ct * 16 * WS_LD + kk * 16, WS_LD);
            wmma::mma_sync(acc, af, bf, acc);
        }

        CP_WAIT(0);
        __syncthreads();
#pragma unroll
        for (int kk = 32; kk < 64; kk++) {
            wmma::fragment<wmma::matrix_a, 16, 16, 16, __half, wmma::row_major> af;
            wmma::fragment<wmma::matrix_b, 16, 16, 16, __half, wmma::col_major> bf;
            wmma::load_matrix_sync(af, shh + rt * 16 * SH_LD + kk * 16, SH_LD);
            wmma::load_matrix_sync(bf, wsB + ct * 16 * WS_LD + kk * 16, WS_LD);
            wmma::mma_sync(acc, af, bf, acc);
        }

        wmma::store_matrix_sync(zsf + rt * 16 * ZS_LD + ct * 16, acc, ZS_LD,
                                wmma::mem_row_major);
        __syncthreads();

        // gate update, cell state in registers
        {
            float zi = zsf[gm0 * ZS_LD + gjj]      + xg0[0] + bb[0];
            float zf = zsf[gm0 * ZS_LD + 8 + gjj]  + xg0[1] + bb[1];
            float zg = zsf[gm0 * ZS_LD + 16 + gjj] + xg0[2] + bb[2];
            float zo = zsf[gm0 * ZS_LD + 24 + gjj] + xg0[3] + bb[3];
            float ig = 1.f / (1.f + __expf(-zi));
            float fg = 1.f / (1.f + __expf(-zf));
            float gg = tanhf(zg);
            float og = 1.f / (1.f + __expf(-zo));
            cc0 = fg * cc0 + ig * gg;
            hout[(size_t)gm0 * Hh + j0 + gjj] = __float2half_rn(og * tanhf(cc0));
        }
        {
            float zi = zsf[gm1 * ZS_LD + gjj]      + xg1[0] + bb[0];
            float zf = zsf[gm1 * ZS_LD + 8 + gjj]  + xg1[1] + bb[1];
            float zg = zsf[gm1 * ZS_LD + 16 + gjj] + xg1[2] + bb[2];
            float zo = zsf[gm1 * ZS_LD + 24 + gjj] + xg1[3] + bb[3];
            float ig = 1.f / (1.f + __expf(-zi));
            float fg = 1.f / (1.f + __expf(-zf));
            float gg = tanhf(zg);
            float og = 1.f / (1.f + __expf(-zo));
            cc1 = fg * cc1 + ig * gg;
            hout[(size_t)gm1 * Hh + j0 + gjj] = __float2half_rn(og * tanhf(cc1));
        }

        // grid barrier: all 128 blocks finish step t before t+1 reads hout
        __threadfence();
        __syncthreads();
        if (tid == 0) {
            atomicAdd(&g_bar, 1u);
            unsigned target = (unsigned)NBLK * (unsigned)(t + 1);
            while (*(volatile unsigned*)&g_bar < target) { }
            __threadfence();
        }
        __syncthreads();
    }
}

// =====================================================================
// Kernel 3: hid = relu(h @ Wd1 + bd1)   (h fp16 row-major [m][k])
// =====================================================================
__global__ __launch_bounds__(256) void k_hid(const float* __restrict__ Wd1,
                                             const float* __restrict__ bd1)
{
    const int gid = blockIdx.x * 256 + threadIdx.x;
    const int m = gid >> 9;
    const int q = gid & 511;
    const __half* __restrict__ h = g_h16[0] + (size_t)m * Hh;  // final h in buf 0
    float s = bd1[q];
#pragma unroll 4
    for (int k = 0; k < Hh; k += 2) {
        __half2 hv = *(const __half2*)(h + k);
        s = fmaf(__low2float(hv),  Wd1[(size_t)k * HD + q], s);
        s = fmaf(__high2float(hv), Wd1[(size_t)(k + 1) * HD + q], s);
    }
    g_hid[gid] = fmaxf(s, 0.f);
}

// =====================================================================
// Kernel 4: out = [hid, actions, horizon] @ Wd2 + bd2   [64, 64]
// =====================================================================
__global__ __launch_bounds__(256) void k_out(const float* __restrict__ actions,
                                             const float* __restrict__ horizon,
                                             const float* __restrict__ Wd2,
                                             const float* __restrict__ bd2,
                                             float* __restrict__ out)
{
    const int gid = blockIdx.x * 256 + threadIdx.x;
    const int m = gid >> 6;
    const int n = gid & 63;
    float s = bd2[n];
#pragma unroll 8
    for (int q = 0; q < HD; q++)
        s = fmaf(g_hid[m * HD + q], Wd2[q * NOUT + n], s);
#pragma unroll
    for (int a = 0; a < Aa; a++)
        s = fmaf(actions[m * Aa + a], Wd2[(HD + a) * NOUT + n], s);
    s = fmaf(horizon[m], Wd2[(HD + Aa) * NOUT + n], s);
    out[gid] = s;
}

// =====================================================================
extern "C" void kernel_launch(void* const* d_in, const int* in_sizes, int n_in,
                              void* d_out, int out_size)
{
    const float* x       = (const float*)d_in[0];
    const float* actions = (const float*)d_in[1];
    const float* horizon = (const float*)d_in[2];
    const float* Wx      = (const float*)d_in[3];
    const float* Wh      = (const float*)d_in[4];
    const float* b       = (const float*)d_in[5];
    const float* Wd1     = (const float*)d_in[6];
    const float* bd1     = (const float*)d_in[7];
    const float* Wd2     = (const float*)d_in[8];
    const float* bd2     = (const float*)d_in[9];
    float* out = (float*)d_out;

    cudaFuncSetAttribute(k_persist, cudaFuncAttributeMaxDynamicSharedMemorySize,
                         P_SMEM);

    void *pH = nullptr, *pB = nullptr;
    cudaGetSymbolAddress(&pH, g_h16);
    cudaGetSymbolAddress(&pB, g_bar);
    cudaMemsetAsync(pH, 0, (size_t)Bq * Hh * sizeof(__half));  // zero h buffer 0
    cudaMemsetAsync(pB, 0, sizeof(unsigned));                  // reset barrier

    // fp16 conversions
    k_cvt_x<<<(MROWS * Ss) / (256 * 4), 256>>>(x);
    k_cvt_wT<<<dim3(G4H / 32, Ss / 32), 256>>>(Wx);

    // x_proj on tensor cores (bias folded into k_persist; [t][b][4H] layout)
    k_xproj_mma<<<dim3(G4H / BN, MROWS / BM), 256>>>();

    // recurrence on tensor cores with cp.async staging
    k_persist<<<NBLK, 256, P_SMEM>>>(Wh, b);

    k_hid<<<128, 256>>>(Wd1, bd1);
    k_out<<<16, 256>>>(actions, horizon, Wd2, bd2, out);
}

// round 16
// speedup vs baseline: 1.0036x; 1.0036x over previous
#include <cuda_runtime.h>
#include <cuda_fp16.h>
#include <mma.h>
#include <math.h>
#include <stdint.h>

using namespace nvcuda;

// Problem constants
#define Bq   64
#define Tt   256
#define Ss   512
#define Hh   1024
#define G4H  4096
#define HD   512
#define Aa   64
#define NOUT 64
#define MROWS (Bq * Tt)   // 16384
#define NBLK 128

// ---------------- scratch (device globals; no runtime allocation) ----------
// g_xp layout: [t][b][4H]  (step-major => per-step reads are one 1MB slab)
__device__ float  g_xp[(size_t)MROWS * G4H];
__device__ __half g_xh[(size_t)MROWS * Ss];    // x in fp16 [16384, 512]
__device__ __half g_wxT[(size_t)G4H * Ss];     // W_x^T in fp16 [4096, 512]
__device__ __half g_h16[2][Bq * Hh];           // ping-pong hidden state fp16, [m][k]
__device__ float  g_hid[Bq * HD];              // relu dense head
__device__ unsigned g_bar;                     // grid barrier counter

// ======================= helpers ========================
__device__ __forceinline__ uint32_t smem_u32(const void* p) {
    uint32_t a;
    asm("{ .reg .u64 t; cvta.to.shared.u64 t, %1; cvt.u32.u64 %0, t; }"
        : "=r"(a) : "l"(p));
    return a;
}
#define CP_ASYNC16(dst, src) \
    asm volatile("cp.async.cg.shared.global [%0], [%1], 16;" :: "r"(dst), "l"(src))
#define CP_COMMIT() asm volatile("cp.async.commit_group;" ::: "memory")
#define CP_WAIT(n)  asm volatile("cp.async.wait_group %0;" :: "n"(n) : "memory")

// =====================================================================
// Conversion: x (fp32) -> g_xh (fp16)
// =====================================================================
__global__ __launch_bounds__(256) void k_cvt_x(const float* __restrict__ X)
{
    size_t i = ((size_t)blockIdx.x * 256 + threadIdx.x) * 4;
    float4 v = *(const float4*)(X + i);
    *(__half2*)(g_xh + i)     = __floats2half2_rn(v.x, v.y);
    *(__half2*)(g_xh + i + 2) = __floats2half2_rn(v.z, v.w);
}

// =====================================================================
// Conversion: W_x [512, 4096] fp32 -> g_wxT [4096, 512] fp16 (transpose)
// =====================================================================
__global__ __launch_bounds__(256) void k_cvt_wT(const float* __restrict__ Wx)
{
    __shared__ float t[32][33];
    const int nb = blockIdx.x * 32;
    const int kb = blockIdx.y * 32;
    const int tx = threadIdx.x & 31;
    const int ty = threadIdx.x >> 5;
#pragma unroll
    for (int r = ty; r < 32; r += 8)
        t[r][tx] = Wx[(size_t)(kb + r) * G4H + nb + tx];
    __syncthreads();
#pragma unroll
    for (int r = ty; r < 32; r += 8)
        g_wxT[(size_t)(nb + r) * Ss + kb + tx] = __float2half_rn(t[tx][r]);
}

// =====================================================================
// Kernel 1: x_proj = x @ W_x via wmma (HMMA fp16, fp32 accumulate).
// Block tile 128x128, BK=32, 8 warps (2m x 4n), warp tile 64x32.
// Output written in [t][b][4H] layout: row r=(b*256+t) -> slab t, row b.
// 16-row tiles never cross a batch boundary (256 % 16 == 0), so
// consecutive tile rows advance t by 1 => ldm = 64*4096.
// =====================================================================
#define BM 128
#define BN 128
#define BK 32
#define LDSB (BK + 8)   // 40 halfs = 80 bytes

__global__ __launch_bounds__(256) void k_xproj_mma()
{
    __shared__ __half sA[BM][LDSB];
    __shared__ __half sB[BN][LDSB];

    const int tid = threadIdx.x;
    const int wid = tid >> 5;
    const int wm  = wid & 1;
    const int wn  = wid >> 1;
    const int bm  = blockIdx.y * BM;
    const int bn  = blockIdx.x * BN;

    wmma::fragment<wmma::accumulator, 16, 16, 16, float> acc[4][2];
#pragma unroll
    for (int i = 0; i < 4; i++)
#pragma unroll
        for (int j = 0; j < 2; j++)
            wmma::fill_fragment(acc[i][j], 0.0f);

    const int sr = tid >> 1;
    const int sc = (tid & 1) * 16;

    for (int k0 = 0; k0 < Ss; k0 += BK) {
        __syncthreads();
        {
            const uint4* sa = (const uint4*)(g_xh  + (size_t)(bm + sr) * Ss + k0 + sc);
            *(uint4*)&sA[sr][sc]     = sa[0];
            *(uint4*)&sA[sr][sc + 8] = sa[1];
            const uint4* sb = (const uint4*)(g_wxT + (size_t)(bn + sr) * Ss + k0 + sc);
            *(uint4*)&sB[sr][sc]     = sb[0];
            *(uint4*)&sB[sr][sc + 8] = sb[1];
        }
        __syncthreads();

#pragma unroll
        for (int kk = 0; kk < BK; kk += 16) {
            wmma::fragment<wmma::matrix_a, 16, 16, 16, __half, wmma::row_major> af[4];
            wmma::fragment<wmma::matrix_b, 16, 16, 16, __half, wmma::col_major> bf[2];
#pragma unroll
            for (int i = 0; i < 4; i++)
                wmma::load_matrix_sync(af[i], &sA[wm * 64 + i * 16][kk], LDSB);
#pragma unroll
            for (int j = 0; j < 2; j++)
                wmma::load_matrix_sync(bf[j], &sB[wn * 32 + j * 16][kk], LDSB);
#pragma unroll
            for (int i = 0; i < 4; i++)
#pragma unroll
                for (int j = 0; j < 2; j++)
                    wmma::mma_sync(acc[i][j], af[i], bf[j], acc[i][j]);
        }
    }

#pragma unroll
    for (int i = 0; i < 4; i++) {
        const int r0 = bm + wm * 64 + i * 16;
        const int t0 = r0 & 255;
        const int b0 = r0 >> 8;
#pragma unroll
        for (int j = 0; j < 2; j++)
            wmma::store_matrix_sync(
                g_xp + ((size_t)t0 * Bq + b0) * G4H + bn + wn * 32 + j * 16,
                acc[i][j], (unsigned)(Bq * G4H), wmma::mem_row_major);
    }
}

// =====================================================================
// Kernel 2: persistent LSTM recurrence on tensor cores.
// 128 blocks x 256 threads. Block b owns 8 hidden units (32 z-columns).
// W_h cols in smem fp16 col-major (once). Per step: cp.async the FULL
// 64x1024 fp16 h tile in 2 commit groups (pipelined against the MMA of
// group 0), 8 warps each compute one 16x16 tile of the 64x32 z-tile,
// gates read the step-t slab of g_xp ([t][b][4H]), grid barrier.
// =====================================================================
#define WS_LD 1032
#define SH_LD 1032
#define ZS_LD 40
#define P_WS_OFF 0
#define P_SH_OFF 66048                      // 32*1032*2
#define P_ZS_OFF (66048 + 132096)           // + 64*1032*2
#define P_SMEM   (P_ZS_OFF + 10240)         // + 64*40*4  = 208384 B

__global__ __launch_bounds__(256, 1) void k_persist(const float* __restrict__ Wh,
                                                    const float* __restrict__ bias)
{
    extern __shared__ char psm[];
    __half* wsB = (__half*)(psm + P_WS_OFF);   // [32][1032] col-major W_h fp16
    __half* shh = (__half*)(psm + P_SH_OFF);   // [64][1032] full h tile fp16
    float*  zsf = (float*)(psm + P_ZS_OFF);    // [64][40]   z tile fp32

    const int tid = threadIdx.x;
    const int j0  = blockIdx.x * 8;

    // ---- stage this block's 32 W_h columns as fp16 (once) ----
    for (int idx = tid; idx < 32768; idx += 256) {
        int c = idx & 31, k = idx >> 5;
        wsB[c * WS_LD + k] =
            __float2half_rn(Wh[(size_t)k * G4H + (c >> 3) * Hh + j0 + (c & 7)]);
    }

    // ---- warp tile mapping (8 warps -> 4 row tiles x 2 col tiles) ----
    const int w  = tid >> 5;
    const int rt = w & 3;          // rows rt*16..+15
    const int ct = w >> 2;         // cols ct*16..+15

    // ---- cp.async staging: per group 4096 16B-units, 16 per thread ----
    const uint32_t shh_u = smem_u32(psm) + P_SH_OFF;

    // ---- gate mapping ----
    const int gjj = tid & 7;
    const int gm0 = tid >> 3;      // 0..31
    const int gm1 = gm0 + 32;
    float bb[4];
#pragma unroll
    for (int g = 0; g < 4; g++) bb[g] = bias[g * Hh + j0 + gjj];

    float cc0 = 0.f, cc1 = 0.f;
    __syncthreads();

    for (int t = 0; t < Tt; t++) {
        const __half* __restrict__ hin  = g_h16[t & 1];
        __half* __restrict__       hout = g_h16[(t + 1) & 1];

        // prefetch xp for the gate phase (step-t slab, contiguous in memory)
        float xg0[4], xg1[4];
#pragma unroll
        for (int g = 0; g < 4; g++) {
            const size_t cb = (size_t)g * Hh + j0 + gjj;
            xg0[g] = g_xp[((size_t)t * Bq + gm0) * G4H + cb];
            xg1[g] = g_xp[((size_t)t * Bq + gm1) * G4H + cb];
        }

        // stage h: two commit groups of 512 cols each
#pragma unroll
        for (int grp = 0; grp < 2; grp++) {
#pragma unroll
            for (int i = 0; i < 16; i++) {
                int u   = i * 256 + tid;
                int row = u >> 6;
                int cu  = u & 63;
                uint32_t dst = shh_u + (uint32_t)(row * SH_LD + grp * 512 + cu * 8) * 2u;
                const __half* src = hin + (size_t)row * Hh + grp * 512 + cu * 8;
                CP_ASYNC16(dst, src);
            }
            CP_COMMIT();
        }

        wmma::fragment<wmma::accumulator, 16, 16, 16, float> acc;
        wmma::fill_fragment(acc, 0.0f);

        CP_WAIT(1);
        __syncthreads();
#pragma unroll
        for (int kk = 0; kk < 32; kk++) {
            wmma::fragment<wmma::matrix_a, 16, 16, 16, __half, wmma::row_major> af;
            wmma::fragment<wmma::matrix_b, 16, 16, 16, __half, wmma::col_major> bf;
            wmma::load_matrix_sync(af, shh + rt * 16 * SH_LD + kk * 16, SH_LD);
            wmma::load_matrix_sync(bf, wsB + ct * 16 * WS_LD + kk * 16, WS_LD);
            wmma::mma_sync(acc, af, bf, acc);
        }

        CP_WAIT(0);
        __syncthreads();
#pragma unroll
        for (int kk = 32; kk < 64; kk++) {
            wmma::fragment<wmma::matrix_a, 16, 16, 16, __half, wmma::row_major> af;
            wmma::fragment<wmma::matrix_b, 16, 16, 16, __half, wmma::col_major> bf;
            wmma::load_matrix_sync(af, shh + rt * 16 * SH_LD + kk * 16, SH_LD);
            wmma::load_matrix_sync(bf, wsB + ct * 16 * WS_LD + kk * 16, WS_LD);
            wmma::mma_sync(acc, af, bf, acc);
        }

        wmma::store_matrix_sync(zsf + rt * 16 * ZS_LD + ct * 16, acc, ZS_LD,
                                wmma::mem_row_major);
        __syncthreads();

        // gate update, cell state in registers
        {
            float zi = zsf[gm0 * ZS_LD + gjj]      + xg0[0] + bb[0];
            float zf = zsf[gm0 * ZS_LD + 8 + gjj]  + xg0[1] + bb[1];
            float zg = zsf[gm0 * ZS_LD + 16 + gjj] + xg0[2] + bb[2];
            float zo = zsf[gm0 * ZS_LD + 24 + gjj] + xg0[3] + bb[3];
            float ig = 1.f / (1.f + __expf(-zi));
            float fg = 1.f / (1.f + __expf(-zf));
            float gg = tanhf(zg);
            float og = 1.f / (1.f + __expf(-zo));
            cc0 = fg * cc0 + ig * gg;
            hout[(size_t)gm0 * Hh + j0 + gjj] = __float2half_rn(og * tanhf(cc0));
        }
        {
            float zi = zsf[gm1 * ZS_LD + gjj]      + xg1[0] + bb[0];
            float zf = zsf[gm1 * ZS_LD + 8 + gjj]  + xg1[1] + bb[1];
            float zg = zsf[gm1 * ZS_LD + 16 + gjj] + xg1[2] + bb[2];
            float zo = zsf[gm1 * ZS_LD + 24 + gjj] + xg1[3] + bb[3];
            float ig = 1.f / (1.f + __expf(-zi));
            float fg = 1.f / (1.f + __expf(-zf));
            float gg = tanhf(zg);
            float og = 1.f / (1.f + __expf(-zo));
            cc1 = fg * cc1 + ig * gg;
            hout[(size_t)gm1 * Hh + j0 + gjj] = __float2half_rn(og * tanhf(cc1));
        }

        // grid barrier: all 128 blocks finish step t before t+1 reads hout
        __threadfence();
        __syncthreads();
        if (tid == 0) {
            atomicAdd(&g_bar, 1u);
            unsigned target = (unsigned)NBLK * (unsigned)(t + 1);
            while (*(volatile unsigned*)&g_bar < target) { }
            __threadfence();
        }
        __syncthreads();
    }
}

// =====================================================================
// Kernel 3: hid = relu(h @ Wd1 + bd1)   (h fp16 row-major [m][k])
// =====================================================================
__global__ __launch_bounds__(256) void k_hid(const float* __restrict__ Wd1,
                                             const float* __restrict__ bd1)
{
    const int gid = blockIdx.x * 256 + threadIdx.x;
    const int m = gid >> 9;
    const int q = gid & 511;
    const __half* __restrict__ h = g_h16[0] + (size_t)m * Hh;  // final h in buf 0
    float s = bd1[q];
#pragma unroll 4
    for (int k = 0; k < Hh; k += 2) {
        __half2 hv = *(const __half2*)(h + k);
        s = fmaf(__low2float(hv),  Wd1[(size_t)k * HD + q], s);
        s = fmaf(__high2float(hv), Wd1[(size_t)(k + 1) * HD + q], s);
    }
    g_hid[gid] = fmaxf(s, 0.f);
}

// =====================================================================
// Kernel 4: out = [hid, actions, horizon] @ Wd2 + bd2   [64, 64]
// =====================================================================
__global__ __launch_bounds__(256) void k_out(const float* __restrict__ actions,
                                             const float* __restrict__ horizon,
                                             const float* __restrict__ Wd2,
                                             const float* __restrict__ bd2,
                                             float* __restrict__ out)
{
    const int gid = blockIdx.x * 256 + threadIdx.x;
    const int m = gid >> 6;
    const int n = gid & 63;
    float s = bd2[n];
#pragma unroll 8
    for (int q = 0; q < HD; q++)
        s = fmaf(g_hid[m * HD + q], Wd2[q * NOUT + n], s);
#pragma unroll
    for (int a = 0; a < Aa; a++)
        s = fmaf(actions[m * Aa + a], Wd2[(HD + a) * NOUT + n], s);
    s = fmaf(horizon[m], Wd2[(HD + Aa) * NOUT + n], s);
    out[gid] = s;
}

// =====================================================================
extern "C" void kernel_launch(void* const* d_in, const int* in_sizes, int n_in,
                              void* d_out, int out_size)
{
    const float* x       = (const float*)d_in[0];
    const float* actions = (const float*)d_in[1];
    const float* horizon = (const float*)d_in[2];
    const float* Wx      = (const float*)d_in[3];
    const float* Wh      = (const float*)d_in[4];
    const float* b       = (const float*)d_in[5];
    const float* Wd1     = (const float*)d_in[6];
    const float* bd1     = (const float*)d_in[7];
    const float* Wd2     = (const float*)d_in[8];
    const float* bd2     = (const float*)d_in[9];
    float* out = (float*)d_out;

    cudaFuncSetAttribute(k_persist, cudaFuncAttributeMaxDynamicSharedMemorySize,
                         P_SMEM);

    void *pH = nullptr, *pB = nullptr;
    cudaGetSymbolAddress(&pH, g_h16);
    cudaGetSymbolAddress(&pB, g_bar);
    cudaMemsetAsync(pH, 0, (size_t)Bq * Hh * sizeof(__half));  // zero h buffer 0
    cudaMemsetAsync(pB, 0, sizeof(unsigned));                  // reset barrier

    // fp16 conversions
    k_cvt_x<<<(MROWS * Ss) / (256 * 4), 256>>>(x);
    k_cvt_wT<<<dim3(G4H / 32, Ss / 32), 256>>>(Wx);

    // x_proj on tensor cores (bias folded into k_persist; [t][b][4H] layout)
    k_xproj_mma<<<dim3(G4H / BN, MROWS / BM), 256>>>();

    // recurrence on tensor cores with cp.async staging
    k_persist<<<NBLK, 256, P_SMEM>>>(Wh, b);

    k_hid<<<128, 256>>>(Wd1, bd1);
    k_out<<<16, 256>>>(actions, horizon, Wd2, bd2, out);
}